// round 5
// baseline (speedup 1.0000x reference)
#include <cuda_runtime.h>

// Problem constants: B=8, N=2048, D=768, two tensors (H, doc_sents_h)
#define DDIM   768
#define NROWS  32768            // 2 * 8 * 2048 source rows
#define ROW4   512              // float4 per output row (2048/4)
#define TOTAL4 16777216LL       // 2*8*2048*2048 / 4 float4 stores

// Scratch: s_src (bias folded in) and s_dst per (tensor, batch, n)
__device__ float g_src[NROWS];
__device__ float g_dst[NROWS];

// Phase 1: one warp per row. Compute X·wa and X·wb in one pass.
__global__ __launch_bounds__(256) void edge_phase1(
    const float* __restrict__ H,
    const float* __restrict__ Dh,
    const float* __restrict__ W,     // [2*DDIM]: wa then wb
    const float* __restrict__ bptr)  // [1]
{
    int r    = blockIdx.x * 8 + (threadIdx.x >> 5);   // row 0..32767
    int lane = threadIdx.x & 31;
    if (r >= NROWS) return;

    const float* X = (r < NROWS / 2) ? (H  + (size_t)r * DDIM)
                                     : (Dh + (size_t)(r - NROWS / 2) * DDIM);
    const float4* X4  = (const float4*)X;
    const float4* Wa4 = (const float4*)W;
    const float4* Wb4 = (const float4*)(W + DDIM);

    float sa = 0.f, sb = 0.f;
    #pragma unroll
    for (int k = 0; k < 6; k++) {                     // 192 float4 per row / 32 lanes
        int idx = lane + k * 32;
        float4 x  = X4[idx];
        float4 wa = __ldg(&Wa4[idx]);
        float4 wb = __ldg(&Wb4[idx]);
        sa = fmaf(x.x, wa.x, fmaf(x.y, wa.y, fmaf(x.z, wa.z, fmaf(x.w, wa.w, sa))));
        sb = fmaf(x.x, wb.x, fmaf(x.y, wb.y, fmaf(x.z, wb.z, fmaf(x.w, wb.w, sb))));
    }
    #pragma unroll
    for (int off = 16; off; off >>= 1) {
        sa += __shfl_xor_sync(0xffffffffu, sa, off);
        sb += __shfl_xor_sync(0xffffffffu, sb, off);
    }
    if (lane == 0) {
        g_src[r] = sa + __ldg(bptr);   // fold bias into the src term
        g_dst[r] = sb;
    }
}

// Phase 2: out[row, j] = relu(s_src[row] + s_dst[group(row), j]).
// Each block handles 1024 consecutive float4 (two output-row halves);
// each thread writes 4 float4 strided by blockDim within the block's tile.
__global__ __launch_bounds__(256) void edge_phase2(float4* __restrict__ out)
{
    const float*  __restrict__ src  = g_src;
    const float4* __restrict__ dst4 = (const float4*)g_dst;

    long long base = (long long)blockIdx.x * 1024;    // 16384 blocks * 1024 = TOTAL4
    #pragma unroll
    for (int it = 0; it < 4; it++) {
        long long v = base + it * 256 + threadIdx.x;
        int row = (int)(v >> 9);                      // /ROW4
        int j4  = (int)(v & (ROW4 - 1));
        float  si = __ldg(&src[row]);
        float4 sd = __ldg(&dst4[((row >> 11) << 9) + j4]);  // group = row/2048, row of 512 float4
        float4 o;
        o.x = fmaxf(si + sd.x, 0.f);
        o.y = fmaxf(si + sd.y, 0.f);
        o.z = fmaxf(si + sd.z, 0.f);
        o.w = fmaxf(si + sd.w, 0.f);
        out[v] = o;
    }
}

extern "C" void kernel_launch(void* const* d_in, const int* in_sizes, int n_in,
                              void* d_out, int out_size)
{
    const float* H  = (const float*)d_in[0];
    const float* Dh = (const float*)d_in[1];
    const float* W  = (const float*)d_in[2];
    const float* b  = (const float*)d_in[3];
    float4* out = (float4*)d_out;

    edge_phase1<<<4096, 256>>>(H, Dh, W, b);   // 32768 rows, 8 warps/block
    edge_phase2<<<16384, 256>>>(out);          // 16384 * 1024 float4 = TOTAL4
}